// round 1
// baseline (speedup 1.0000x reference)
#include <cuda_runtime.h>

#define N_NODES 50000
#define D_FEAT  128
#define N_EDGES 800000
#define ROW_F4  (D_FEAT / 4)   // 32 float4 per row

// Scratch (allocation-free rule: __device__ globals)
__device__ float4 g_pooled[N_NODES * ROW_F4];   // 25.6 MB accumulator
__device__ float  g_deg_out[N_NODES];
__device__ float  g_deg_in[N_NODES];

// ---------------------------------------------------------------------------
// K0: zero accumulator + degree arrays
// ---------------------------------------------------------------------------
__global__ void zero_kernel() {
    const int stride = gridDim.x * blockDim.x;
    int i = blockIdx.x * blockDim.x + threadIdx.x;
    const float4 z = make_float4(0.f, 0.f, 0.f, 0.f);
    for (int j = i; j < N_NODES * ROW_F4; j += stride)
        g_pooled[j] = z;
    for (int j = i; j < N_NODES; j += stride) {
        g_deg_out[j] = 0.f;
        g_deg_in[j]  = 0.f;
    }
}

// ---------------------------------------------------------------------------
// K1: degree histograms (RED.ADD, no return value used)
// ---------------------------------------------------------------------------
__global__ void deg_kernel(const int* __restrict__ src,
                           const int* __restrict__ tgt) {
    int e = blockIdx.x * blockDim.x + threadIdx.x;
    if (e < N_EDGES) {
        atomicAdd(&g_deg_out[src[e]], 1.0f);
        atomicAdd(&g_deg_in[tgt[e]], 1.0f);
    }
}

// ---------------------------------------------------------------------------
// K2: edge scatter. One warp per edge; lane l owns float4 l of the 128-wide
// row. Sender scale folded in. Vector red.global.add.v4.f32 (sm_90+) cuts
// L2 atomic op count 4x vs scalar atomicAdd.
// ---------------------------------------------------------------------------
__global__ __launch_bounds__(256) void scatter_kernel(
        const float4* __restrict__ x,
        const int* __restrict__ src,
        const int* __restrict__ tgt) {
    int warp = (blockIdx.x * blockDim.x + threadIdx.x) >> 5;
    int lane = threadIdx.x & 31;
    if (warp >= N_EDGES) return;

    int s = __ldg(&src[warp]);   // same addr per warp -> 1 sector
    int t = __ldg(&tgt[warp]);
    float scale = rsqrtf(fmaxf(__ldg(&g_deg_out[s]), 1.0f));

    float4 v = __ldg(&x[s * ROW_F4 + lane]);
    v.x *= scale; v.y *= scale; v.z *= scale; v.w *= scale;

    float* p = reinterpret_cast<float*>(&g_pooled[t * ROW_F4 + lane]);
    asm volatile("red.global.add.v4.f32 [%0], {%1, %2, %3, %4};"
                 :: "l"(p), "f"(v.x), "f"(v.y), "f"(v.z), "f"(v.w)
                 : "memory");
}

// ---------------------------------------------------------------------------
// K3: out = relu( (rsqrt(deg_in) * pooled) @ W + b )
// Row scaling commutes with the matmul -> applied in epilogue.
// Block: 512 threads, tile 128 rows x 128 cols, K in chunks of 32.
// Thread (tx = tid%32 -> 4 cols, ty = tid/32 -> 8 rows): 8x4 fp32 micro-tile.
// A-operand smem reads are warp-uniform broadcasts (all lanes share ty).
// ---------------------------------------------------------------------------
#define G_ROWS 128
#define G_KC   32

__global__ __launch_bounds__(512) void gemm_kernel(
        const float* __restrict__ W,      // [128,128] row-major (k, j)
        const float4* __restrict__ b4,    // [32] float4 = 128 bias
        float4* __restrict__ out) {       // [N_NODES * 32]
    __shared__ float As[G_ROWS * G_KC];   // 16 KB  (row-major [row][k])
    __shared__ float Ws[G_KC * D_FEAT];   // 16 KB  (row-major [k][j])

    const int tid = threadIdx.x;
    const int tx  = tid & 31;        // col group: cols tx*4 .. tx*4+3
    const int ty  = tid >> 5;        // row group: rows ty*8 .. ty*8+7
    const int row_base = blockIdx.x * G_ROWS;

    float4 acc[8];
#pragma unroll
    for (int i = 0; i < 8; i++) acc[i] = make_float4(0.f, 0.f, 0.f, 0.f);

    const float4* poolv = g_pooled;

    for (int c = 0; c < D_FEAT / G_KC; c++) {
        // ---- load A chunk: 128 rows x 32 k = 1024 float4; 512 thr x 2 ----
#pragma unroll
        for (int pass = 0; pass < 2; pass++) {
            int idx = pass * 512 + tid;          // 0..1023
            int r   = idx >> 3;                  // 0..127
            int f4  = idx & 7;                   // 0..7  (k/4 within chunk)
            int grow = row_base + r;
            float4 v = make_float4(0.f, 0.f, 0.f, 0.f);
            if (grow < N_NODES)
                v = poolv[grow * ROW_F4 + c * (G_KC / 4) + f4];
            *reinterpret_cast<float4*>(&As[r * G_KC + f4 * 4]) = v;
        }
        // ---- load W chunk: 32 k x 128 j = 1024 float4 ----
#pragma unroll
        for (int pass = 0; pass < 2; pass++) {
            int idx = pass * 512 + tid;
            int kk  = idx >> 5;                  // 0..31
            int f4  = idx & 31;                  // 0..31
            float4 v = *reinterpret_cast<const float4*>(
                &W[(c * G_KC + kk) * D_FEAT + f4 * 4]);
            *reinterpret_cast<float4*>(&Ws[kk * D_FEAT + f4 * 4]) = v;
        }
        __syncthreads();

        // ---- compute ----
#pragma unroll
        for (int kk = 0; kk < G_KC; kk++) {
            float4 w = *reinterpret_cast<const float4*>(&Ws[kk * D_FEAT + tx * 4]);
            float a[8];
#pragma unroll
            for (int i = 0; i < 8; i++)
                a[i] = As[(ty * 8 + i) * G_KC + kk];   // warp-uniform broadcast
#pragma unroll
            for (int i = 0; i < 8; i++) {
                acc[i].x = fmaf(a[i], w.x, acc[i].x);
                acc[i].y = fmaf(a[i], w.y, acc[i].y);
                acc[i].z = fmaf(a[i], w.z, acc[i].z);
                acc[i].w = fmaf(a[i], w.w, acc[i].w);
            }
        }
        __syncthreads();
    }

    // ---- epilogue: receiver scale, bias, relu ----
    float4 bias = __ldg(&b4[tx]);
#pragma unroll
    for (int i = 0; i < 8; i++) {
        int r = row_base + ty * 8 + i;
        if (r >= N_NODES) continue;
        float scale = rsqrtf(fmaxf(g_deg_in[r], 1.0f));
        float4 o;
        o.x = fmaxf(fmaf(acc[i].x, scale, bias.x), 0.f);
        o.y = fmaxf(fmaf(acc[i].y, scale, bias.y), 0.f);
        o.z = fmaxf(fmaf(acc[i].z, scale, bias.z), 0.f);
        o.w = fmaxf(fmaf(acc[i].w, scale, bias.w), 0.f);
        out[r * ROW_F4 + tx] = o;
    }
}

// ---------------------------------------------------------------------------
// Inputs (metadata order): x [N,D] f32, source [E] i32, target [E] i32,
// W [D,U] f32, b [U] f32. Output: [N, U] f32.
// ---------------------------------------------------------------------------
extern "C" void kernel_launch(void* const* d_in, const int* in_sizes, int n_in,
                              void* d_out, int out_size) {
    const float4* x   = (const float4*)d_in[0];
    const int*    src = (const int*)d_in[1];
    const int*    tgt = (const int*)d_in[2];
    const float*  W   = (const float*)d_in[3];
    const float4* b   = (const float4*)d_in[4];
    float4* out = (float4*)d_out;

    zero_kernel<<<2048, 256>>>();
    deg_kernel<<<(N_EDGES + 255) / 256, 256>>>(src, tgt);
    // one warp per edge: 8 warps per 256-thread block
    scatter_kernel<<<(N_EDGES + 7) / 8, 256>>>(x, src, tgt);
    gemm_kernel<<<(N_NODES + G_ROWS - 1) / G_ROWS, 512>>>(W, b, out);
}